// round 16
// baseline (speedup 1.0000x reference)
#include <cuda_runtime.h>
#include <cuda_fp16.h>
#include <cstdint>

#define BB   512
#define ENC  512
#define ATT  512
#define ND   1024

typedef unsigned long long ull;

// ==================== fp32 scratch ====================
__device__ float g_att1p[4 * BB * ATT];   // x@We (K split 4)
__device__ float g_att2p[4 * BB * ATT];   // state@Wd (K split 4)
__device__ float g_stp  [4 * BB * ND];    // state@W2 (K split 4)
__device__ float g_att1 [BB * ATT];       // (att1+be)*Wf prescaled
__device__ float g_att2 [BB * ATT];       // (att2+bd)*Wf prescaled
__device__ float g_S    [1024];           // rowsums for rank-1 softmax base
__device__ float g_attp [8 * BB * BB];    // Σ±|u| partials (channel split 8)
__device__ float g_awep [4 * BB * ENC];   // alpha@x partials (K split 4)
__device__ float g_inpp [4 * BB * ND];    // iw@W1 partials (K split 4)

// ==================== fp16 operands (single term) ====================
__device__ __align__(16) __half g_xh [BB * ENC];
__device__ __align__(16) __half g_sth[BB * ND];
__device__ __align__(16) __half g_alh[BB * BB];
__device__ __align__(16) __half g_iwh[BB * ENC];
__device__ __align__(16) __half g_WeT[ATT * ENC];
__device__ __align__(16) __half g_WdT[ATT * ND];
__device__ __align__(16) __half g_W2T[ND * ND];
__device__ __align__(16) __half g_W1T[ND * ENC];
__device__ __align__(16) __half g_xT [ENC * BB];

// ==================== helpers ====================
__device__ __forceinline__ uint32_t smem_u32(const void* p) {
    uint32_t a;
    asm("{ .reg .u64 t; cvta.to.shared.u64 t, %1; cvt.u32.u64 %0, t; }" : "=r"(a) : "l"(p));
    return a;
}
__device__ __forceinline__ ull add2(ull a, ull b) {
    ull r; asm("add.rn.f32x2 %0, %1, %2;" : "=l"(r) : "l"(a), "l"(b)); return r;
}
union F2U { ull u; float2 f; };
union U4  { float4 f; ull u[2]; };

// ==================== warp-mma GEMM, plain fp16, 2-stage (R10-validated) ====================
#define SST    40
#define TILEB  (128 * SST * 2)
#define STAGEB (2 * TILEB)
#define WG_SMEM (2 * STAGEB)

__device__ __forceinline__ void wg_load(uint32_t sbase,
        const __half* __restrict__ Ap, const __half* __restrict__ Bp,
        int lda, int ldb, int kofs, int buf) {
    const int tid = threadIdx.x;
    const __half* srcs[2] = {Ap, Bp};
    const int lds[2] = {lda, ldb};
    #pragma unroll
    for (int m2 = 0; m2 < 2; m2++) {
        #pragma unroll
        for (int j = 0; j < 2; j++) {
            int c = tid + j * 256;
            int row = c >> 2, c4 = c & 3;
            const __half* s = srcs[m2] + (size_t)row * lds[m2] + kofs + c4 * 8;
            uint32_t d = sbase + buf * STAGEB + m2 * TILEB + (uint32_t)(row * SST + c4 * 8) * 2;
            asm volatile("cp.async.cg.shared.global [%0], [%1], 16;" :: "r"(d), "l"(s));
        }
    }
    asm volatile("cp.async.commit_group;");
}

#define LDM_X4(r, addr) \
    asm volatile("ldmatrix.sync.aligned.m8n8.x4.shared.b16 {%0,%1,%2,%3}, [%4];" \
        : "=r"((r)[0]), "=r"((r)[1]), "=r"((r)[2]), "=r"((r)[3]) : "r"(addr))
#define MMA16816(acc, a, b0, b1) \
    asm volatile("mma.sync.aligned.m16n8k16.row.col.f32.f16.f16.f32 " \
        "{%0,%1,%2,%3}, {%4,%5,%6,%7}, {%8,%9}, {%0,%1,%2,%3};" \
        : "+f"((acc)[0]), "+f"((acc)[1]), "+f"((acc)[2]), "+f"((acc)[3]) \
        : "r"((a)[0]), "r"((a)[1]), "r"((a)[2]), "r"((a)[3]), "r"(b0), "r"(b1))

__device__ void wgemm(const __half* __restrict__ A, const __half* __restrict__ B, int K,
                      float* __restrict__ C, int ldc,
                      int bm, int bn, int k0, int ksz) {
    extern __shared__ __align__(16) char smem[];
    const uint32_t sbase = smem_u32(smem);
    const int tid = threadIdx.x;
    const int lane = tid & 31, wid = tid >> 5;
    const int wm = wid >> 2, wn = wid & 3;

    const __half* Ap = A + (size_t)bm * K + k0;
    const __half* Bp = B + (size_t)bn * K + k0;

    float acc[4][4][4];
    #pragma unroll
    for (int i = 0; i < 4; i++)
        #pragma unroll
        for (int j = 0; j < 4; j++)
            #pragma unroll
            for (int r = 0; r < 4; r++) acc[i][j][r] = 0.0f;

    const int T = ksz >> 5;
    wg_load(sbase, Ap, Bp, K, K, 0, 0);

    for (int t = 0; t < T; t++) {
        if (t + 1 < T) {
            wg_load(sbase, Ap, Bp, K, K, (t + 1) * 32, (t + 1) & 1);
            asm volatile("cp.async.wait_group 1;" ::: "memory");
        } else {
            asm volatile("cp.async.wait_group 0;" ::: "memory");
        }
        __syncthreads();
        const uint32_t stg = sbase + (uint32_t)(t & 1) * STAGEB;
        #pragma unroll
        for (int s = 0; s < 2; s++) {
            const int kc = s * 16;
            const int arow = wm * 64 + (lane & 15);
            const int acol = kc + ((lane >> 4) << 3);
            const int brow = wn * 32 + (lane & 7) + ((lane >> 4) << 3);
            const int bcol = kc + (((lane >> 3) & 1) << 3);

            uint32_t ah[4][4], bh[2][4];
            #pragma unroll
            for (int mt = 0; mt < 4; mt++)
                LDM_X4(ah[mt], stg + 0 * TILEB + (uint32_t)((arow + mt * 16) * SST + acol) * 2);
            #pragma unroll
            for (int p = 0; p < 2; p++)
                LDM_X4(bh[p], stg + 1 * TILEB + (uint32_t)((brow + p * 16) * SST + bcol) * 2);
            #pragma unroll
            for (int mt = 0; mt < 4; mt++)
                #pragma unroll
                for (int nt = 0; nt < 4; nt++)
                    MMA16816(acc[mt][nt], ah[mt], bh[nt >> 1][(nt & 1) * 2], bh[nt >> 1][(nt & 1) * 2 + 1]);
        }
        __syncthreads();
    }
    #pragma unroll
    for (int mt = 0; mt < 4; mt++) {
        int r0 = bm + wm * 64 + mt * 16 + (lane >> 2);
        #pragma unroll
        for (int nt = 0; nt < 4; nt++) {
            int c = bn + wn * 32 + nt * 8 + (lane & 3) * 2;
            *(float2*)&C[(size_t)r0 * ldc + c]       = make_float2(acc[mt][nt][0], acc[mt][nt][1]);
            *(float2*)&C[(size_t)(r0 + 8) * ldc + c] = make_float2(acc[mt][nt][2], acc[mt][nt][3]);
        }
    }
}

// ---- GEMM phase wrappers ----
__global__ __launch_bounds__(256, 2) void wp1_kernel() {
    int id = blockIdx.x;
    if (id < 64) {                 // att1 = x @ We : K=512 split 4
        int ks = id >> 4, t = id & 15;
        wgemm(g_xh, g_WeT, ENC, g_att1p + (size_t)ks * BB * ATT, ATT,
              (t & 3) * 128, (t >> 2) * 128, ks * 128, 128);
    } else if (id < 128) {         // att2 = state @ Wd : K=1024 split 4
        int t = id - 64, ks = t >> 4, u = t & 15;
        wgemm(g_sth, g_WdT, ND, g_att2p + (size_t)ks * BB * ATT, ATT,
              (u & 3) * 128, (u >> 2) * 128, ks * 256, 256);
    } else {                       // st = state @ W2 : K=1024 split 4
        int t = id - 128, ks = t >> 5, u = t & 31;
        wgemm(g_sth, g_W2T, ND, g_stp + (size_t)ks * BB * ND, ND,
              (u & 3) * 128, ((u >> 2) & 7) * 128, ks * 256, 256);
    }
}
__global__ __launch_bounds__(256, 2) void wp4_kernel() {   // awe = alpha @ x : K=512 split 4
    int id = blockIdx.x;
    int ks = id >> 4, t = id & 15;
    wgemm(g_alh, g_xT, BB, g_awep + (size_t)ks * BB * ENC, ENC,
          (t & 3) * 128, (t >> 2) * 128, ks * 128, 128);
}
__global__ __launch_bounds__(256, 2) void wp5_kernel() {   // inp = iw @ W1 : K=512 split 4
    int id = blockIdx.x;
    int ks = id >> 5, t = id & 31;
    wgemm(g_iwh, g_W1T, ENC, g_inpp + (size_t)ks * BB * ND, ND,
          (t & 3) * 128, ((t >> 2) & 7) * 128, ks * 128, 128);
}

// ==================== prep: fp32 -> fp16 ====================
__global__ __launch_bounds__(256) void prep_kernel(const float* __restrict__ x,
        const float* __restrict__ state, const float* __restrict__ We,
        const float* __restrict__ Wd, const float* __restrict__ W2,
        const float* __restrict__ W1) {
    __shared__ float tile[32][33];
    int b = blockIdx.x;
    if (b < 2560) {    // B-side: transpose [K][N] -> dst[n][K]
        const float* src; __half* dst; int K, N, t0;
        if (b < 256)       { src = We; dst = g_WeT; K = ENC; N = ATT; t0 = b; }
        else if (b < 768)  { src = Wd; dst = g_WdT; K = ND;  N = ATT; t0 = b - 256; }
        else if (b < 1792) { src = W2; dst = g_W2T; K = ND;  N = ND;  t0 = b - 768; }
        else if (b < 2304) { src = W1; dst = g_W1T; K = ENC; N = ND;  t0 = b - 1792; }
        else               { src = x;  dst = g_xT;  K = BB;  N = ENC; t0 = b - 2304; }
        int tiles_n = N >> 5;
        int tk = t0 / tiles_n, tn = t0 - tk * tiles_n;
        int k0 = tk * 32, n0 = tn * 32;
        int tx = threadIdx.x & 31, ty = threadIdx.x >> 5;
        #pragma unroll
        for (int i = 0; i < 4; i++)
            tile[ty + 8 * i][tx] = src[(size_t)(k0 + ty + 8 * i) * N + n0 + tx];
        __syncthreads();
        #pragma unroll
        for (int i = 0; i < 4; i++) {
            float v = tile[tx][ty + 8 * i];
            dst[(size_t)(n0 + ty + 8 * i) * K + k0 + tx] = __float2half_rn(v);
        }
    } else {           // A-side: [r][K] fp32 -> fp16
        const float* src; __half* dst; int off;
        if (b < 2688) { src = x;     dst = g_xh;  off = (b - 2560) * 2048; }
        else          { src = state; dst = g_sth; off = (b - 2688) * 2048; }
        int base = off + threadIdx.x * 8;
        float4 v0 = *(const float4*)&src[base];
        float4 v1 = *(const float4*)&src[base + 4];
        __half2 h0 = make_half2(__float2half_rn(v0.x), __float2half_rn(v0.y));
        __half2 h1 = make_half2(__float2half_rn(v0.z), __float2half_rn(v0.w));
        __half2 h2 = make_half2(__float2half_rn(v1.x), __float2half_rn(v1.y));
        __half2 h3 = make_half2(__float2half_rn(v1.z), __float2half_rn(v1.w));
        *(uint4*)&dst[base] = *(uint4*)&(__half2[4]){h0, h1, h2, h3};
    }
}

// ==================== combineA: prescale + per-row sums for rank-1 base ====================
__global__ __launch_bounds__(256) void combineA_kernel(const float* __restrict__ be,
        const float* __restrict__ bd, const float* __restrict__ Wf) {
    const int b = blockIdx.x, tid = threadIdx.x;
    const int Q = BB * ATT / 4;
    float4 v4; int srow;
    if (b < 256) {                 // att1 rows (index k): 4 partials
        int g = b * 256 + tid;
        int c4 = g & (ATT / 4 - 1);
        float4 bb = ((const float4*)be)[c4];
        float4 w = ((const float4*)Wf)[c4];
        const float4* p = (const float4*)g_att1p;
        float4 a0 = p[g], a1 = p[g + Q], a2 = p[g + 2 * Q], a3 = p[g + 3 * Q];
        v4 = make_float4((a0.x + a1.x + a2.x + a3.x + bb.x) * w.x,
                         (a0.y + a1.y + a2.y + a3.y + bb.y) * w.y,
                         (a0.z + a1.z + a2.z + a3.z + bb.z) * w.z,
                         (a0.w + a1.w + a2.w + a3.w + bb.w) * w.w);
        ((float4*)g_att1)[g] = v4;
        srow = g >> 7;
    } else {                       // att2 rows (index q): 4 partials
        int g = (b - 256) * 256 + tid;
        const float4* p = (const float4*)g_att2p;
        float4 a0 = p[g], a1 = p[g + Q], a2 = p[g + 2 * Q], a3 = p[g + 3 * Q];
        int c4 = g & (ATT / 4 - 1);
        float4 bb = ((const float4*)bd)[c4];
        float4 w = ((const float4*)Wf)[c4];
        v4 = make_float4((a0.x + a1.x + a2.x + a3.x + bb.x) * w.x,
                         (a0.y + a1.y + a2.y + a3.y + bb.y) * w.y,
                         (a0.z + a1.z + a2.z + a3.z + bb.z) * w.z,
                         (a0.w + a1.w + a2.w + a3.w + bb.w) * w.w);
        ((float4*)g_att2)[g] = v4;
        srow = 512 + (g >> 7);
    }
    float s = v4.x + v4.y + v4.z + v4.w;
    #pragma unroll
    for (int o = 16; o; o >>= 1) s += __shfl_xor_sync(~0u, s, o);
    __shared__ float ws[8];
    if ((tid & 31) == 0) ws[tid >> 5] = s;
    __syncthreads();
    if (tid == 0)   g_S[srow] = ws[0] + ws[1] + ws[2] + ws[3];
    if (tid == 128) g_S[srow] = ws[4] + ws[5] + ws[6] + ws[7];
}

// ==================== attention core (z-split 8, 64k x 64q tiles, 3 CTAs/SM) ============
// thread tile: 4q x 4k. per cc: 1 vec LDS + 2 bcast LDS + 8 add2 + 16 FADD.abs
__global__ __launch_bounds__(256, 3) void attcore_kernel(const float* __restrict__ Wf) {
    __shared__ __align__(16) float A1[16][68];      // [c][k]   64k + pad
    __shared__ __align__(16) float A2[16][132];     // [c][2q]  dup pairs, 128 + pad
    __shared__ float wsg[16];
    const int tid = threadIdx.x;
    const int tk = tid & 15;          // k: 4 at tk*4
    const int tq = tid >> 4;          // q: 4 at tq*4
    const int bk = blockIdx.x * 64, bq = blockIdx.y * 64;
    const int c0base = blockIdx.z * 64;

    float acc[4][4];
    #pragma unroll
    for (int i = 0; i < 4; i++)
        #pragma unroll
        for (int j = 0; j < 4; j++) acc[i][j] = 0.0f;

    for (int ct = 0; ct < 4; ct++) {
        const int cb = c0base + ct * 16;
        // A1 fill: 16c x 64k = 1024 elems, 4/thread
        #pragma unroll
        for (int i = 0; i < 4; i++) {
            int idx = tid + i * 256;
            int c = idx & 15, k = idx >> 4;
            A1[c][k] = g_att1[(size_t)(bk + k) * ATT + cb + c];
        }
        // A2 fill duplicated: 16c x 64q, 4/thread
        #pragma unroll
        for (int i = 0; i < 4; i++) {
            int idx = tid + i * 256;
            int c = idx & 15, q = idx >> 4;
            float v = g_att2[(size_t)(bq + q) * ATT + cb + c];
            *(float2*)&A2[c][2 * q] = make_float2(v, v);
        }
        if (tid < 16) wsg[tid] = Wf[cb + tid];
        __syncthreads();

        #pragma unroll
        for (int cc = 0; cc < 16; cc++) {
            U4 a1v; a1v.f = *(const float4*)&A1[cc][tk * 4];       // 2 k-pairs
            U4 q01, q23;                                           // 4 dup q-pairs
            q01.f = *(const float4*)&A2[cc][8 * tq + 0];
            q23.f = *(const float4*)&A2[cc][8 * tq + 4];
            ull qd[4] = { q01.u[0], q01.u[1], q23.u[0], q23.u[1] };
            if (wsg[cc] > 0.0f) {
                #pragma unroll
                for (int q = 0; q < 4; q++)
                    #pragma unroll
                    for (int p = 0; p < 2; p++) {
                        F2U t; t.u = add2(a1v.u[p], qd[q]);
                        acc[q][2 * p]     += fabsf(t.f.x);
                        acc[q][2 * p + 1] += fabsf(t.f.y);
                    }
            } else {
                #pragma unroll
                for (int q = 0; q < 4; q++)
                    #pragma unroll
                    for (int p = 0; p < 2; p++) {
                        F2U t; t.u = add2(a1v.u[p], qd[q]);
                        acc[q][2 * p]     -= fabsf(t.f.x);
                        acc[q][2 * p + 1] -= fabsf(t.f.y);
                    }
            }
        }
        __syncthreads();
    }
    float* out = g_attp + (size_t)blockIdx.z * BB * BB;
    #pragma unroll
    for (int q = 0; q < 4; q++) {
        float4 v = make_float4(acc[q][0], acc[q][1], acc[q][2], acc[q][3]);
        *(float4*)&out[(size_t)(bq + tq * 4 + q) * BB + bk + tk * 4] = v;
    }
}

// ==================== softmax: logits = 0.5*(S1[k]+S2[q]+Σ partials) -> alpha fp16 ======
__global__ void softmax_kernel() {
    const int row = blockIdx.x;
    const int t = threadIdx.x;   // 128 threads, float4 each
    __shared__ float red[4];
    const size_t Q = (size_t)BB * BB;
    const size_t base = (size_t)row * BB + t * 4;
    float4 s4 = make_float4(0.f, 0.f, 0.f, 0.f);
    #pragma unroll
    for (int z = 0; z < 8; z++) {
        float4 p = *(const float4*)&g_attp[base + z * Q];
        s4.x += p.x; s4.y += p.y; s4.z += p.z; s4.w += p.w;
    }
    float4 S1v = *(const float4*)&g_S[t * 4];
    float S2 = g_S[512 + row];
    s4.x = 0.5f * (s4.x + S1v.x + S2);
    s4.y = 0.5f * (s4.y + S1v.y + S2);
    s4.z = 0.5f * (s4.z + S1v.z + S2);
    s4.w = 0.5f * (s4.w + S1v.w + S2);
    float m = fmaxf(fmaxf(s4.x, s4.y), fmaxf(s4.z, s4.w));
    #pragma unroll
    for (int o = 16; o; o >>= 1) m = fmaxf(m, __shfl_xor_sync(~0u, m, o));
    if ((t & 31) == 0) red[t >> 5] = m;
    __syncthreads();
    m = fmaxf(fmaxf(red[0], red[1]), fmaxf(red[2], red[3]));
    s4.x = __expf(s4.x - m); s4.y = __expf(s4.y - m);
    s4.z = __expf(s4.z - m); s4.w = __expf(s4.w - m);
    float s = s4.x + s4.y + s4.z + s4.w;
    #pragma unroll
    for (int o = 16; o; o >>= 1) s += __shfl_xor_sync(~0u, s, o);
    __syncthreads();
    if ((t & 31) == 0) red[t >> 5] = s;
    __syncthreads();
    s = red[0] + red[1] + red[2] + red[3];
    float inv = 1.0f / s;
    __half2 h0 = make_half2(__float2half_rn(s4.x * inv), __float2half_rn(s4.y * inv));
    __half2 h1 = make_half2(__float2half_rn(s4.z * inv), __float2half_rn(s4.w * inv));
    *(uint2*)&g_alh[(size_t)row * BB + t * 4] = *(uint2*)&(__half2[2]){h0, h1};
}

// ==================== iw = (Σ awep) * x -> fp16 ====================
__global__ void combine_iw_kernel(const float* __restrict__ x) {
    int g = blockIdx.x * blockDim.x + threadIdx.x;
    const int Q = BB * ENC / 4;
    const float4* p = (const float4*)g_awep;
    float4 a0 = p[g], a1 = p[g + Q], a2 = p[g + 2 * Q], a3 = p[g + 3 * Q];
    float4 xv = ((const float4*)x)[g];
    __half2 h0 = make_half2(__float2half_rn((a0.x + a1.x + a2.x + a3.x) * xv.x),
                            __float2half_rn((a0.y + a1.y + a2.y + a3.y) * xv.y));
    __half2 h1 = make_half2(__float2half_rn((a0.z + a1.z + a2.z + a3.z) * xv.z),
                            __float2half_rn((a0.w + a1.w + a2.w + a3.w) * xv.w));
    *(uint2*)&g_iwh[g * 4] = *(uint2*)&(__half2[2]){h0, h1};
}

// ==================== fused: new_state + output ====================
__global__ __launch_bounds__(256) void ns_out_kernel(const float* __restrict__ b1,
        const float* __restrict__ b2, const float* __restrict__ W3,
        const float* __restrict__ b3, float* __restrict__ new_state,
        float* __restrict__ out) {
    const int row = blockIdx.x;
    const int tid = threadIdx.x;
    const int g = row * 256 + tid;
    const int Q = BB * ND / 4;
    const float4* ip = (const float4*)g_inpp;
    const float4* sp = (const float4*)g_stp;
    float4 i0 = ip[g], i1 = ip[g + Q], i2 = ip[g + 2 * Q], i3 = ip[g + 3 * Q];
    float4 s0 = sp[g], s1 = sp[g + Q], s2 = sp[g + 2 * Q], s3 = sp[g + 3 * Q];
    float4 bb1 = ((const float4*)b1)[tid];
    float4 bb2 = ((const float4*)b2)[tid];
    float4 o;
    o.x = fmaxf(i0.x + i1.x + i2.x + i3.x + s0.x + s1.x + s2.x + s3.x + bb1.x + bb2.x, 0.f);
    o.y = fmaxf(i0.y + i1.y + i2.y + i3.y + s0.y + s1.y + s2.y + s3.y + bb1.y + bb2.y, 0.f);
    o.z = fmaxf(i0.z + i1.z + i2.z + i3.z + s0.z + s1.z + s2.z + s3.z + bb1.z + bb2.z, 0.f);
    o.w = fmaxf(i0.w + i1.w + i2.w + i3.w + s0.w + s1.w + s2.w + s3.w + bb1.w + bb2.w, 0.f);
    ((float4*)new_state)[g] = o;
    int c = tid * 4;
    float4 w0 = *(const float4*)&W3[c * 2];
    float4 w1 = *(const float4*)&W3[c * 2 + 4];
    float d0 = o.x * w0.x + o.y * w0.z + o.z * w1.x + o.w * w1.z;
    float d1 = o.x * w0.y + o.y * w0.w + o.z * w1.y + o.w * w1.w;
    #pragma unroll
    for (int of = 16; of; of >>= 1) {
        d0 += __shfl_xor_sync(~0u, d0, of);
        d1 += __shfl_xor_sync(~0u, d1, of);
    }
    __shared__ float rs[8][2];
    if ((tid & 31) == 0) { rs[tid >> 5][0] = d0; rs[tid >> 5][1] = d1; }
    __syncthreads();
    if (tid == 0) {
        float t0 = 0.f, t1 = 0.f;
        #pragma unroll
        for (int w = 0; w < 8; w++) { t0 += rs[w][0]; t1 += rs[w][1]; }
        out[row * 2 + 0] = t0 + b3[0];
        out[row * 2 + 1] = t1 + b3[1];
    }
}

// ==================== launch (serialized — validated R10 structure) ====================
extern "C" void kernel_launch(void* const* d_in, const int* in_sizes, int n_in,
                              void* d_out, int out_size) {
    const float* x     = (const float*)d_in[0];
    const float* state = (const float*)d_in[1];
    const float* We    = (const float*)d_in[2];
    const float* be    = (const float*)d_in[3];
    const float* Wd    = (const float*)d_in[4];
    const float* bd    = (const float*)d_in[5];
    const float* Wf    = (const float*)d_in[6];
    // d_in[7] = bf : constant shift of all softmax logits -> mathematically irrelevant
    const float* W1    = (const float*)d_in[8];
    const float* b1    = (const float*)d_in[9];
    const float* W2    = (const float*)d_in[10];
    const float* b2    = (const float*)d_in[11];
    const float* W3    = (const float*)d_in[12];
    const float* b3    = (const float*)d_in[13];

    float* out = (float*)d_out;            // [0,1024): output ; then new_state (512x1024)
    float* new_state = out + BB * 2;

    cudaFuncSetAttribute(wp1_kernel, cudaFuncAttributeMaxDynamicSharedMemorySize, WG_SMEM);
    cudaFuncSetAttribute(wp4_kernel, cudaFuncAttributeMaxDynamicSharedMemorySize, WG_SMEM);
    cudaFuncSetAttribute(wp5_kernel, cudaFuncAttributeMaxDynamicSharedMemorySize, WG_SMEM);

    prep_kernel<<<2944, 256>>>(x, state, We, Wd, W2, W1);
    wp1_kernel<<<256, 256, WG_SMEM>>>();
    combineA_kernel<<<512, 256>>>(be, bd, Wf);
    attcore_kernel<<<dim3(8, 8, 8), 256>>>(Wf);
    softmax_kernel<<<BB, 128>>>();
    wp4_kernel<<<64, 256, WG_SMEM>>>();
    combine_iw_kernel<<<256, 256>>>(x);
    wp5_kernel<<<128, 256, WG_SMEM>>>();
    ns_out_kernel<<<BB, 256>>>(b1, b2, W3, b3, new_state, out);
}

// round 17
// speedup vs baseline: 1.0686x; 1.0686x over previous
#include <cuda_runtime.h>
#include <cuda_fp16.h>
#include <cstdint>

#define BB   512
#define ENC  512
#define ATT  512
#define ND   1024

typedef unsigned long long ull;

// ==================== fp32 scratch ====================
__device__ float g_att1p[4 * BB * ATT];   // x@We (K split 4)
__device__ float g_att2p[4 * BB * ATT];   // state@Wd (K split 4)
__device__ float g_stp  [4 * BB * ND];    // state@W2 (K split 4)
__device__ float g_att1 [BB * ATT];       // (att1+be)*Wf prescaled
__device__ float g_att2 [BB * ATT];       // (att2+bd)*Wf prescaled
__device__ float g_S    [1024];           // rowsums for rank-1 softmax base
__device__ float g_attp [8 * BB * BB];    // Σ±|u| partials (channel split 8)
__device__ float g_awep [4 * BB * ENC];   // alpha@x partials (K split 4)
__device__ float g_inpp [4 * BB * ND];    // iw@W1 partials (K split 4)

// ==================== fp16 operands (single term) ====================
__device__ __align__(16) __half g_xh [BB * ENC];
__device__ __align__(16) __half g_sth[BB * ND];
__device__ __align__(16) __half g_alh[BB * BB];
__device__ __align__(16) __half g_iwh[BB * ENC];
__device__ __align__(16) __half g_WeT[ATT * ENC];
__device__ __align__(16) __half g_WdT[ATT * ND];
__device__ __align__(16) __half g_W2T[ND * ND];
__device__ __align__(16) __half g_W1T[ND * ENC];
__device__ __align__(16) __half g_xT [ENC * BB];

// ==================== helpers ====================
__device__ __forceinline__ uint32_t smem_u32(const void* p) {
    uint32_t a;
    asm("{ .reg .u64 t; cvta.to.shared.u64 t, %1; cvt.u32.u64 %0, t; }" : "=r"(a) : "l"(p));
    return a;
}
__device__ __forceinline__ ull add2(ull a, ull b) {
    ull r; asm("add.rn.f32x2 %0, %1, %2;" : "=l"(r) : "l"(a), "l"(b)); return r;
}
union F2U { ull u; float2 f; };
union U4  { float4 f; ull u[2]; };

// ==================== warp-mma GEMM, fp16, KT=64 stages (fewer barriers) ====================
#define SST    72                         // fp16 row stride: 144 B ≡ 16 mod 128 -> conflict-free ldmatrix
#define TILEB  (128 * SST * 2)            // 128x64 fp16 tile (18432 B)
#define STAGEB (2 * TILEB)                // A + B   (36864 B)
#define WG_SMEM (2 * STAGEB)              // double buffered (73728 B), 2 CTAs/SM

__device__ __forceinline__ void wg_load(uint32_t sbase,
        const __half* __restrict__ Ap, const __half* __restrict__ Bp,
        int lda, int ldb, int kofs, int buf) {
    const int tid = threadIdx.x;
    const __half* srcs[2] = {Ap, Bp};
    const int lds[2] = {lda, ldb};
    #pragma unroll
    for (int m2 = 0; m2 < 2; m2++) {
        #pragma unroll
        for (int j = 0; j < 4; j++) {
            int c = tid + j * 256;
            int row = c >> 3, c8 = c & 7;
            const __half* s = srcs[m2] + (size_t)row * lds[m2] + kofs + c8 * 8;
            uint32_t d = sbase + buf * STAGEB + m2 * TILEB + (uint32_t)(row * SST + c8 * 8) * 2;
            asm volatile("cp.async.cg.shared.global [%0], [%1], 16;" :: "r"(d), "l"(s));
        }
    }
    asm volatile("cp.async.commit_group;");
}

#define LDM_X4(r, addr) \
    asm volatile("ldmatrix.sync.aligned.m8n8.x4.shared.b16 {%0,%1,%2,%3}, [%4];" \
        : "=r"((r)[0]), "=r"((r)[1]), "=r"((r)[2]), "=r"((r)[3]) : "r"(addr))
#define MMA16816(acc, a, b0, b1) \
    asm volatile("mma.sync.aligned.m16n8k16.row.col.f32.f16.f16.f32 " \
        "{%0,%1,%2,%3}, {%4,%5,%6,%7}, {%8,%9}, {%0,%1,%2,%3};" \
        : "+f"((acc)[0]), "+f"((acc)[1]), "+f"((acc)[2]), "+f"((acc)[3]) \
        : "r"((a)[0]), "r"((a)[1]), "r"((a)[2]), "r"((a)[3]), "r"(b0), "r"(b1))

__device__ void wgemm(const __half* __restrict__ A, const __half* __restrict__ B, int K,
                      float* __restrict__ C, int ldc,
                      int bm, int bn, int k0, int ksz) {
    extern __shared__ __align__(16) char smem[];
    const uint32_t sbase = smem_u32(smem);
    const int tid = threadIdx.x;
    const int lane = tid & 31, wid = tid >> 5;
    const int wm = wid >> 2, wn = wid & 3;

    const __half* Ap = A + (size_t)bm * K + k0;
    const __half* Bp = B + (size_t)bn * K + k0;

    float acc[4][4][4];
    #pragma unroll
    for (int i = 0; i < 4; i++)
        #pragma unroll
        for (int j = 0; j < 4; j++)
            #pragma unroll
            for (int r = 0; r < 4; r++) acc[i][j][r] = 0.0f;

    const int T = ksz >> 6;               // KT = 64
    wg_load(sbase, Ap, Bp, K, K, 0, 0);

    for (int t = 0; t < T; t++) {
        if (t + 1 < T) {
            wg_load(sbase, Ap, Bp, K, K, (t + 1) * 64, (t + 1) & 1);
            asm volatile("cp.async.wait_group 1;" ::: "memory");
        } else {
            asm volatile("cp.async.wait_group 0;" ::: "memory");
        }
        __syncthreads();
        const uint32_t stg = sbase + (uint32_t)(t & 1) * STAGEB;
        #pragma unroll
        for (int s = 0; s < 4; s++) {
            const int kc = s * 16;
            const int arow = wm * 64 + (lane & 15);
            const int acol = kc + ((lane >> 4) << 3);
            const int brow = wn * 32 + (lane & 7) + ((lane >> 4) << 3);
            const int bcol = kc + (((lane >> 3) & 1) << 3);

            uint32_t ah[4][4], bh[2][4];
            #pragma unroll
            for (int mt = 0; mt < 4; mt++)
                LDM_X4(ah[mt], stg + 0 * TILEB + (uint32_t)((arow + mt * 16) * SST + acol) * 2);
            #pragma unroll
            for (int p = 0; p < 2; p++)
                LDM_X4(bh[p], stg + 1 * TILEB + (uint32_t)((brow + p * 16) * SST + bcol) * 2);
            #pragma unroll
            for (int mt = 0; mt < 4; mt++)
                #pragma unroll
                for (int nt = 0; nt < 4; nt++)
                    MMA16816(acc[mt][nt], ah[mt], bh[nt >> 1][(nt & 1) * 2], bh[nt >> 1][(nt & 1) * 2 + 1]);
        }
        __syncthreads();
    }
    #pragma unroll
    for (int mt = 0; mt < 4; mt++) {
        int r0 = bm + wm * 64 + mt * 16 + (lane >> 2);
        #pragma unroll
        for (int nt = 0; nt < 4; nt++) {
            int c = bn + wn * 32 + nt * 8 + (lane & 3) * 2;
            *(float2*)&C[(size_t)r0 * ldc + c]       = make_float2(acc[mt][nt][0], acc[mt][nt][1]);
            *(float2*)&C[(size_t)(r0 + 8) * ldc + c] = make_float2(acc[mt][nt][2], acc[mt][nt][3]);
        }
    }
}

// ---- GEMM phase wrappers ----
__global__ __launch_bounds__(256, 2) void wp1_kernel() {
    int id = blockIdx.x;
    if (id < 64) {                 // att1 = x @ We : K=512 split 4
        int ks = id >> 4, t = id & 15;
        wgemm(g_xh, g_WeT, ENC, g_att1p + (size_t)ks * BB * ATT, ATT,
              (t & 3) * 128, (t >> 2) * 128, ks * 128, 128);
    } else if (id < 128) {         // att2 = state @ Wd : K=1024 split 4
        int t = id - 64, ks = t >> 4, u = t & 15;
        wgemm(g_sth, g_WdT, ND, g_att2p + (size_t)ks * BB * ATT, ATT,
              (u & 3) * 128, (u >> 2) * 128, ks * 256, 256);
    } else {                       // st = state @ W2 : K=1024 split 4
        int t = id - 128, ks = t >> 5, u = t & 31;
        wgemm(g_sth, g_W2T, ND, g_stp + (size_t)ks * BB * ND, ND,
              (u & 3) * 128, ((u >> 2) & 7) * 128, ks * 256, 256);
    }
}
__global__ __launch_bounds__(256, 2) void wp4_kernel() {   // awe = alpha @ x : K=512 split 4
    int id = blockIdx.x;
    int ks = id >> 4, t = id & 15;
    wgemm(g_alh, g_xT, BB, g_awep + (size_t)ks * BB * ENC, ENC,
          (t & 3) * 128, (t >> 2) * 128, ks * 128, 128);
}
__global__ __launch_bounds__(256, 2) void wp5_kernel() {   // inp = iw @ W1 : K=512 split 4
    int id = blockIdx.x;
    int ks = id >> 5, t = id & 31;
    wgemm(g_iwh, g_W1T, ENC, g_inpp + (size_t)ks * BB * ND, ND,
          (t & 3) * 128, ((t >> 2) & 7) * 128, ks * 128, 128);
}

// ==================== prep: fp32 -> fp16 ====================
__global__ __launch_bounds__(256) void prep_kernel(const float* __restrict__ x,
        const float* __restrict__ state, const float* __restrict__ We,
        const float* __restrict__ Wd, const float* __restrict__ W2,
        const float* __restrict__ W1) {
    __shared__ float tile[32][33];
    int b = blockIdx.x;
    if (b < 2560) {    // B-side: transpose [K][N] -> dst[n][K]
        const float* src; __half* dst; int K, N, t0;
        if (b < 256)       { src = We; dst = g_WeT; K = ENC; N = ATT; t0 = b; }
        else if (b < 768)  { src = Wd; dst = g_WdT; K = ND;  N = ATT; t0 = b - 256; }
        else if (b < 1792) { src = W2; dst = g_W2T; K = ND;  N = ND;  t0 = b - 768; }
        else if (b < 2304) { src = W1; dst = g_W1T; K = ENC; N = ND;  t0 = b - 1792; }
        else               { src = x;  dst = g_xT;  K = BB;  N = ENC; t0 = b - 2304; }
        int tiles_n = N >> 5;
        int tk = t0 / tiles_n, tn = t0 - tk * tiles_n;
        int k0 = tk * 32, n0 = tn * 32;
        int tx = threadIdx.x & 31, ty = threadIdx.x >> 5;
        #pragma unroll
        for (int i = 0; i < 4; i++)
            tile[ty + 8 * i][tx] = src[(size_t)(k0 + ty + 8 * i) * N + n0 + tx];
        __syncthreads();
        #pragma unroll
        for (int i = 0; i < 4; i++) {
            float v = tile[tx][ty + 8 * i];
            dst[(size_t)(n0 + ty + 8 * i) * K + k0 + tx] = __float2half_rn(v);
        }
    } else {           // A-side: [r][K] fp32 -> fp16
        const float* src; __half* dst; int off;
        if (b < 2688) { src = x;     dst = g_xh;  off = (b - 2560) * 2048; }
        else          { src = state; dst = g_sth; off = (b - 2688) * 2048; }
        int base = off + threadIdx.x * 8;
        float4 v0 = *(const float4*)&src[base];
        float4 v1 = *(const float4*)&src[base + 4];
        __half2 h0 = make_half2(__float2half_rn(v0.x), __float2half_rn(v0.y));
        __half2 h1 = make_half2(__float2half_rn(v0.z), __float2half_rn(v0.w));
        __half2 h2 = make_half2(__float2half_rn(v1.x), __float2half_rn(v1.y));
        __half2 h3 = make_half2(__float2half_rn(v1.z), __float2half_rn(v1.w));
        *(uint4*)&dst[base] = *(uint4*)&(__half2[4]){h0, h1, h2, h3};
    }
}

// ==================== combineA: prescale + per-row sums for rank-1 base ====================
__global__ __launch_bounds__(256) void combineA_kernel(const float* __restrict__ be,
        const float* __restrict__ bd, const float* __restrict__ Wf) {
    const int b = blockIdx.x, tid = threadIdx.x;
    const int Q = BB * ATT / 4;
    float4 v4; int srow;
    if (b < 256) {                 // att1 rows (index k): 4 partials
        int g = b * 256 + tid;
        int c4 = g & (ATT / 4 - 1);
        float4 bb = ((const float4*)be)[c4];
        float4 w = ((const float4*)Wf)[c4];
        const float4* p = (const float4*)g_att1p;
        float4 a0 = p[g], a1 = p[g + Q], a2 = p[g + 2 * Q], a3 = p[g + 3 * Q];
        v4 = make_float4((a0.x + a1.x + a2.x + a3.x + bb.x) * w.x,
                         (a0.y + a1.y + a2.y + a3.y + bb.y) * w.y,
                         (a0.z + a1.z + a2.z + a3.z + bb.z) * w.z,
                         (a0.w + a1.w + a2.w + a3.w + bb.w) * w.w);
        ((float4*)g_att1)[g] = v4;
        srow = g >> 7;
    } else {                       // att2 rows (index q): 4 partials
        int g = (b - 256) * 256 + tid;
        const float4* p = (const float4*)g_att2p;
        float4 a0 = p[g], a1 = p[g + Q], a2 = p[g + 2 * Q], a3 = p[g + 3 * Q];
        int c4 = g & (ATT / 4 - 1);
        float4 bb = ((const float4*)bd)[c4];
        float4 w = ((const float4*)Wf)[c4];
        v4 = make_float4((a0.x + a1.x + a2.x + a3.x + bb.x) * w.x,
                         (a0.y + a1.y + a2.y + a3.y + bb.y) * w.y,
                         (a0.z + a1.z + a2.z + a3.z + bb.z) * w.z,
                         (a0.w + a1.w + a2.w + a3.w + bb.w) * w.w);
        ((float4*)g_att2)[g] = v4;
        srow = 512 + (g >> 7);
    }
    float s = v4.x + v4.y + v4.z + v4.w;
    #pragma unroll
    for (int o = 16; o; o >>= 1) s += __shfl_xor_sync(~0u, s, o);
    __shared__ float ws[8];
    if ((tid & 31) == 0) ws[tid >> 5] = s;
    __syncthreads();
    if (tid == 0)   g_S[srow] = ws[0] + ws[1] + ws[2] + ws[3];
    if (tid == 128) g_S[srow] = ws[4] + ws[5] + ws[6] + ws[7];
}

// ==================== attention core: partials = Σ_c ±|a1'+a2'| (R10-validated) ============
__global__ __launch_bounds__(256, 2) void attcore_kernel(const float* __restrict__ Wf) {
    __shared__ __align__(16) float A1[16][132];
    __shared__ __align__(16) float A2[16][132];
    __shared__ float wsg[16];
    const int tid = threadIdx.x;
    const int tx = tid & 31;
    const int ty = tid >> 5;
    const int bk = blockIdx.x * 128, bq = blockIdx.y * 64;
    const int c0base = blockIdx.z * 64;

    float acc[8][4];
    #pragma unroll
    for (int i = 0; i < 8; i++)
        #pragma unroll
        for (int j = 0; j < 4; j++) acc[i][j] = 0.0f;

    for (int ct = 0; ct < 4; ct++) {
        const int cb = c0base + ct * 16;
        #pragma unroll
        for (int i = 0; i < 8; i++) {
            int idx = tid + i * 256;
            int c = idx & 15, k = idx >> 4;
            A1[c][k] = g_att1[(size_t)(bk + k) * ATT + cb + c];
        }
        #pragma unroll
        for (int i = 0; i < 4; i++) {
            int idx = tid + i * 256;
            int c = idx & 15, q = idx >> 4;
            float v = g_att2[(size_t)(bq + q) * ATT + cb + c];
            *(float2*)&A2[c][2 * q] = make_float2(v, v);
        }
        if (tid < 16) wsg[tid] = Wf[cb + tid];
        __syncthreads();

        #pragma unroll
        for (int cc = 0; cc < 16; cc++) {
            U4 a1v; a1v.f = *(const float4*)&A1[cc][tx * 4];
            U4 q01, q23, q45, q67;
            q01.f = *(const float4*)&A2[cc][16 * ty + 0];
            q23.f = *(const float4*)&A2[cc][16 * ty + 4];
            q45.f = *(const float4*)&A2[cc][16 * ty + 8];
            q67.f = *(const float4*)&A2[cc][16 * ty + 12];
            ull qd[8] = { q01.u[0], q01.u[1], q23.u[0], q23.u[1],
                          q45.u[0], q45.u[1], q67.u[0], q67.u[1] };
            if (wsg[cc] > 0.0f) {
                #pragma unroll
                for (int q = 0; q < 8; q++)
                    #pragma unroll
                    for (int p = 0; p < 2; p++) {
                        F2U t; t.u = add2(a1v.u[p], qd[q]);
                        acc[q][2 * p]     += fabsf(t.f.x);
                        acc[q][2 * p + 1] += fabsf(t.f.y);
                    }
            } else {
                #pragma unroll
                for (int q = 0; q < 8; q++)
                    #pragma unroll
                    for (int p = 0; p < 2; p++) {
                        F2U t; t.u = add2(a1v.u[p], qd[q]);
                        acc[q][2 * p]     -= fabsf(t.f.x);
                        acc[q][2 * p + 1] -= fabsf(t.f.y);
                    }
            }
        }
        __syncthreads();
    }
    float* out = g_attp + (size_t)blockIdx.z * BB * BB;
    #pragma unroll
    for (int q = 0; q < 8; q++) {
        float4 v = make_float4(acc[q][0], acc[q][1], acc[q][2], acc[q][3]);
        *(float4*)&out[(size_t)(bq + ty * 8 + q) * BB + bk + tx * 4] = v;
    }
}

// ==================== softmax: logits = 0.5*(S1[k]+S2[q]+Σ partials) -> alpha fp16 ======
__global__ void softmax_kernel() {
    const int row = blockIdx.x;
    const int t = threadIdx.x;   // 128 threads, float4 each
    __shared__ float red[4];
    const size_t Q = (size_t)BB * BB;
    const size_t base = (size_t)row * BB + t * 4;
    float4 s4 = make_float4(0.f, 0.f, 0.f, 0.f);
    #pragma unroll
    for (int z = 0; z < 8; z++) {
        float4 p = *(const float4*)&g_attp[base + z * Q];
        s4.x += p.x; s4.y += p.y; s4.z += p.z; s4.w += p.w;
    }
    float4 S1v = *(const float4*)&g_S[t * 4];
    float S2 = g_S[512 + row];
    s4.x = 0.5f * (s4.x + S1v.x + S2);
    s4.y = 0.5f * (s4.y + S1v.y + S2);
    s4.z = 0.5f * (s4.z + S1v.z + S2);
    s4.w = 0.5f * (s4.w + S1v.w + S2);
    float m = fmaxf(fmaxf(s4.x, s4.y), fmaxf(s4.z, s4.w));
    #pragma unroll
    for (int o = 16; o; o >>= 1) m = fmaxf(m, __shfl_xor_sync(~0u, m, o));
    if ((t & 31) == 0) red[t >> 5] = m;
    __syncthreads();
    m = fmaxf(fmaxf(red[0], red[1]), fmaxf(red[2], red[3]));
    s4.x = __expf(s4.x - m); s4.y = __expf(s4.y - m);
    s4.z = __expf(s4.z - m); s4.w = __expf(s4.w - m);
    float s = s4.x + s4.y + s4.z + s4.w;
    #pragma unroll
    for (int o = 16; o; o >>= 1) s += __shfl_xor_sync(~0u, s, o);
    __syncthreads();
    if ((t & 31) == 0) red[t >> 5] = s;
    __syncthreads();
    s = red[0] + red[1] + red[2] + red[3];
    float inv = 1.0f / s;
    __half2 h0 = make_half2(__float2half_rn(s4.x * inv), __float2half_rn(s4.y * inv));
    __half2 h1 = make_half2(__float2half_rn(s4.z * inv), __float2half_rn(s4.w * inv));
    *(uint2*)&g_alh[(size_t)row * BB + t * 4] = *(uint2*)&(__half2[2]){h0, h1};
}

// ==================== iw = (Σ awep) * x -> fp16 ====================
__global__ void combine_iw_kernel(const float* __restrict__ x) {
    int g = blockIdx.x * blockDim.x + threadIdx.x;
    const int Q = BB * ENC / 4;
    const float4* p = (const float4*)g_awep;
    float4 a0 = p[g], a1 = p[g + Q], a2 = p[g + 2 * Q], a3 = p[g + 3 * Q];
    float4 xv = ((const float4*)x)[g];
    __half2 h0 = make_half2(__float2half_rn((a0.x + a1.x + a2.x + a3.x) * xv.x),
                            __float2half_rn((a0.y + a1.y + a2.y + a3.y) * xv.y));
    __half2 h1 = make_half2(__float2half_rn((a0.z + a1.z + a2.z + a3.z) * xv.z),
                            __float2half_rn((a0.w + a1.w + a2.w + a3.w) * xv.w));
    *(uint2*)&g_iwh[g * 4] = *(uint2*)&(__half2[2]){h0, h1};
}

// ==================== fused: new_state + output ====================
__global__ __launch_bounds__(256) void ns_out_kernel(const float* __restrict__ b1,
        const float* __restrict__ b2, const float* __restrict__ W3,
        const float* __restrict__ b3, float* __restrict__ new_state,
        float* __restrict__ out) {
    const int row = blockIdx.x;
    const int tid = threadIdx.x;
    const int g = row * 256 + tid;
    const int Q = BB * ND / 4;
    const float4* ip = (const float4*)g_inpp;
    const float4* sp = (const float4*)g_stp;
    float4 i0 = ip[g], i1 = ip[g + Q], i2 = ip[g + 2 * Q], i3 = ip[g + 3 * Q];
    float4 s0 = sp[g], s1 = sp[g + Q], s2 = sp[g + 2 * Q], s3 = sp[g + 3 * Q];
    float4 bb1 = ((const float4*)b1)[tid];
    float4 bb2 = ((const float4*)b2)[tid];
    float4 o;
    o.x = fmaxf(i0.x + i1.x + i2.x + i3.x + s0.x + s1.x + s2.x + s3.x + bb1.x + bb2.x, 0.f);
    o.y = fmaxf(i0.y + i1.y + i2.y + i3.y + s0.y + s1.y + s2.y + s3.y + bb1.y + bb2.y, 0.f);
    o.z = fmaxf(i0.z + i1.z + i2.z + i3.z + s0.z + s1.z + s2.z + s3.z + bb1.z + bb2.z, 0.f);
    o.w = fmaxf(i0.w + i1.w + i2.w + i3.w + s0.w + s1.w + s2.w + s3.w + bb1.w + bb2.w, 0.f);
    ((float4*)new_state)[g] = o;
    int c = tid * 4;
    float4 w0 = *(const float4*)&W3[c * 2];
    float4 w1 = *(const float4*)&W3[c * 2 + 4];
    float d0 = o.x * w0.x + o.y * w0.z + o.z * w1.x + o.w * w1.z;
    float d1 = o.x * w0.y + o.y * w0.w + o.z * w1.y + o.w * w1.w;
    #pragma unroll
    for (int of = 16; of; of >>= 1) {
        d0 += __shfl_xor_sync(~0u, d0, of);
        d1 += __shfl_xor_sync(~0u, d1, of);
    }
    __shared__ float rs[8][2];
    if ((tid & 31) == 0) { rs[tid >> 5][0] = d0; rs[tid >> 5][1] = d1; }
    __syncthreads();
    if (tid == 0) {
        float t0 = 0.f, t1 = 0.f;
        #pragma unroll
        for (int w = 0; w < 8; w++) { t0 += rs[w][0]; t1 += rs[w][1]; }
        out[row * 2 + 0] = t0 + b3[0];
        out[row * 2 + 1] = t1 + b3[1];
    }
}

// ==================== launch (serialized — validated R10 structure) ====================
extern "C" void kernel_launch(void* const* d_in, const int* in_sizes, int n_in,
                              void* d_out, int out_size) {
    const float* x     = (const float*)d_in[0];
    const float* state = (const float*)d_in[1];
    const float* We    = (const float*)d_in[2];
    const float* be    = (const float*)d_in[3];
    const float* Wd    = (const float*)d_in[4];
    const float* bd    = (const float*)d_in[5];
    const float* Wf    = (const float*)d_in[6];
    // d_in[7] = bf : constant shift of all softmax logits -> mathematically irrelevant
    const float* W1    = (const float*)d_in[8];
    const float* b1    = (const float*)d_in[9];
    const float* W2    = (const float*)d_in[10];
    const float* b2    = (const float*)d_in[11];
    const float* W3    = (const float*)d_in[12];
    const float* b3    = (const float*)d_in[13];

    float* out = (float*)d_out;            // [0,1024): output ; then new_state (512x1024)
    float* new_state = out + BB * 2;

    cudaFuncSetAttribute(wp1_kernel, cudaFuncAttributeMaxDynamicSharedMemorySize, WG_SMEM);
    cudaFuncSetAttribute(wp4_kernel, cudaFuncAttributeMaxDynamicSharedMemorySize, WG_SMEM);
    cudaFuncSetAttribute(wp5_kernel, cudaFuncAttributeMaxDynamicSharedMemorySize, WG_SMEM);

    prep_kernel<<<2944, 256>>>(x, state, We, Wd, W2, W1);
    wp1_kernel<<<256, 256, WG_SMEM>>>();
    combineA_kernel<<<512, 256>>>(be, bd, Wf);
    attcore_kernel<<<dim3(4, 8, 8), 256>>>(Wf);
    softmax_kernel<<<BB, 128>>>();
    wp4_kernel<<<64, 256, WG_SMEM>>>();
    combine_iw_kernel<<<256, 256>>>(x);
    wp5_kernel<<<128, 256, WG_SMEM>>>();
    ns_out_kernel<<<BB, 256>>>(b1, b2, W3, b3, new_state, out);
}